// round 13
// baseline (speedup 1.0000x reference)
#include <cuda_runtime.h>
#include <cstdint>

#define HIDDEN    1024
#define MOE_FF    512
#define SHARED_FF 2816
#define NE        16
#define NTOK      2048
#define NENT      (2*NTOK)

// ---------------- scratch (device globals; no allocation allowed) ----------
__device__ float g_GU [NTOK * (2 * SHARED_FF)]; // shared gate|up raw acc [m][5632]
__device__ float g_GUe[NENT * HIDDEN];          // expert gate|up raw acc [ent][1024]
__device__ float g_H1[NTOK * SHARED_FF];        // shared-expert hidden (tf32-rounded)
__device__ float g_Hx[NENT * MOE_FF];           // expert hidden per entry (tf32)
__device__ float g_partial[NENT * HIDDEN];      // weighted expert out per entry
__device__ int   g_list[NE][NTOK];              // entry id (2n+k) per expert bucket
__device__ int   g_cnt[NE];
__device__ float g_wts[NENT];                   // renormalized router weight
__device__ float g_sig[NTOK];                   // shared-expert sigmoid gate

__device__ __forceinline__ float silu_f(float v) { return v / (1.f + __expf(-v)); }
__device__ __forceinline__ float to_tf32(float x) {
    float y; asm("cvt.rna.tf32.f32 %0, %1;" : "=f"(y) : "f"(x)); return y;
}

// m16n8k8 TF32 HMMA (generic PTX — valid on target sm_103)
__device__ __forceinline__ void mma8(float* c, const uint32_t* a, const uint32_t* b) {
    asm volatile(
        "mma.sync.aligned.m16n8k8.row.col.f32.tf32.tf32.f32 "
        "{%0,%1,%2,%3}, {%4,%5,%6,%7}, {%8,%9}, {%0,%1,%2,%3};"
        : "+f"(c[0]), "+f"(c[1]), "+f"(c[2]), "+f"(c[3])
        : "r"(a[0]), "r"(a[1]), "r"(a[2]), "r"(a[3]), "r"(b[0]), "r"(b[1]));
}

__device__ __forceinline__ uint32_t smem_u32(const void* p) {
    uint32_t a;
    asm("{ .reg .u64 t; cvta.to.shared.u64 t, %1; cvt.u32.u64 %0, t; }" : "=r"(a) : "l"(p));
    return a;
}
#define CP_ASYNC16(dst, src) \
    asm volatile("cp.async.cg.shared.global [%0], [%1], 16;" :: "r"(dst), "l"(src))
#define CP_COMMIT() asm volatile("cp.async.commit_group;" ::: "memory")
#define CP_WAIT(n)  asm volatile("cp.async.wait_group %0;" :: "n"(n) : "memory")

// ---------------- misc ------------------------------------------------------
__global__ void k_zero_cnt() {
    if (threadIdx.x < NE) g_cnt[threadIdx.x] = 0;
}

// ---------------- router: logits -> top2 -> renorm weights + buckets --------
__global__ void k_router(const float* __restrict__ x,
                         const float* __restrict__ gw,
                         const float* __restrict__ sgw) {
    int n = blockIdx.x;
    int t = threadIdx.x;
    float xv[8];
#pragma unroll
    for (int i = 0; i < 8; i++) xv[i] = x[n * HIDDEN + t + i * 128];

    __shared__ float red[17 * 4];
    for (int e = 0; e < 17; e++) {
        const float* wr = (e < 16) ? (gw + e * HIDDEN) : sgw;
        float s = 0.f;
#pragma unroll
        for (int i = 0; i < 8; i++) s += xv[i] * wr[t + i * 128];
#pragma unroll
        for (int o = 16; o; o >>= 1) s += __shfl_xor_sync(0xffffffffu, s, o);
        if ((t & 31) == 0) red[e * 4 + (t >> 5)] = s;
    }
    __syncthreads();
    if (t == 0) {
        float lg[17];
        for (int e = 0; e < 17; e++)
            lg[e] = red[e * 4] + red[e * 4 + 1] + red[e * 4 + 2] + red[e * 4 + 3];
        int i0 = 0;
        for (int e = 1; e < 16; e++) if (lg[e] > lg[i0]) i0 = e;
        int i1 = -1;
        for (int e = 0; e < 16; e++) {
            if (e == i0) continue;
            if (i1 < 0 || lg[e] > lg[i1]) i1 = e;
        }
        float m  = lg[i0];
        float e0 = expf(lg[i0] - m);
        float e1 = expf(lg[i1] - m);
        float inv = 1.f / (e0 + e1);
        g_wts[2 * n]     = e0 * inv;
        g_wts[2 * n + 1] = e1 * inv;
        int p0 = atomicAdd(&g_cnt[i0], 1); g_list[i0][p0] = 2 * n;
        int p1 = atomicAdd(&g_cnt[i1], 1); g_list[i1][p1] = 2 * n + 1;
        g_sig[n] = 1.f / (1.f + expf(-lg[16]));
    }
}

// ---------------- single-mode TF32 HMMA GEMM --------------------------------
// CTA 128x64, 8 warps 4Mx2N, warp 32x32 (acc 32 regs), BK=32, 2-stage
// cp.async ring, 1 barrier per chunk, __launch_bounds__(256,3) -> 24 warps/SM.
// A smem [m][k] LDA=36; B smem: modes 0/1 [n][k] LDA=36; modes 2/3 [k][n]
// LDN=72. All fragment LDS conflict-free.
// MODE 0: A=X (cvt), B per-n-block swg|swu [n][k], C=g_GU raw (ld 5632)
// MODE 1: A=g_H1 (pre-rounded), B=swd [n][k], C=out * g_sig
// MODE 2: A=X gathered (cvt), B=wgu[e] [k][n], C=g_GUe raw (ld 1024)
// MODE 3: A=g_Hx gathered, B=wdn[e] [k][n], C=g_partial * g_wts
template<int KTOT, int MODE>
__global__ void __launch_bounds__(256, 3)
k_mma(const float* __restrict__ Ag, const float* __restrict__ Bg,
      const float* __restrict__ B2g, float* __restrict__ Cg)
{
    constexpr int NK      = KTOT / 32;
    constexpr int NSTAGE  = 2;
    constexpr int LDA     = 36;                         // floats
    constexpr int ABYTES  = 128 * LDA * 4;              // 18432
    constexpr int LDN     = 72;                         // [k][n] stride, modes>=2
    constexpr int BBYTES  = 9216;                       // 64*36*4 == 32*72*4
    constexpr int STAGE   = ABYTES + BBYTES;            // 27648
    constexpr bool CVT_A  = (MODE == 0 || MODE == 2);
    constexpr int LDB_G   = (MODE == 0) ? HIDDEN : SHARED_FF; // modes 0/1

    extern __shared__ char smem_buf[];
    const uint32_t sb0 = smem_u32(smem_buf);

    const int t   = threadIdx.x;
    const int wid = t >> 5, lid = t & 31;
    const int wm  = wid & 3, wn = wid >> 2;
    const int g   = lid >> 2, tg = lid & 3;
    const int bn  = blockIdx.x * 64, bm = blockIdx.y * 128;

    int Me = 0; const int* lst = nullptr; size_t bbase = 0;
    if constexpr (MODE >= 2) {
        int e = blockIdx.z;
        Me = g_cnt[e];
        if (bm >= Me) return;
        lst = g_list[e];
        bbase = (size_t)e * KTOT * 1024;
    }

    // MODE0: B pointer + local n selected per n-block (gate cols <SHARED_FF)
    const float* Brow = Bg;
    int bnl = bn;
    if constexpr (MODE == 0) {
        if (bn >= SHARED_FF) { Brow = B2g; bnl = bn - SHARED_FF; }
    }

    // A fill assignment: thread covers rows fr+32i (i=0..3), 16B slot fj
    const int fj = t & 7, fr = t >> 3;
    const float* arow[4];
#pragma unroll
    for (int i = 0; i < 4; i++) {
        int row = fr + 32 * i;
        if constexpr (MODE == 0)      arow[i] = Ag   + (size_t)(bm + row) * HIDDEN;
        else if constexpr (MODE == 1) arow[i] = g_H1 + (size_t)(bm + row) * SHARED_FF;
        else {
            int m = bm + row; if (m > Me - 1) m = Me - 1;
            int ent = lst[m];
            if constexpr (MODE == 2) arow[i] = Ag   + (size_t)(ent >> 1) * HIDDEN;
            else                     arow[i] = g_Hx + (size_t)ent * MOE_FF;
        }
    }

    // ---- pipelined fill of one stage ----
    auto fill = [&](int kc) {
        const int k0 = kc * 32;
        const uint32_t sa = sb0 + (uint32_t)((kc & 1) * STAGE);
#pragma unroll
        for (int i = 0; i < 4; i++)
            CP_ASYNC16(sa + (uint32_t)((fr + 32 * i) * (LDA * 4) + fj * 16),
                       arow[i] + k0 + fj * 4);
        if constexpr (MODE <= 1) {
#pragma unroll
            for (int i = 0; i < 2; i++) {
                int row = fr + 32 * i;
                CP_ASYNC16(sa + ABYTES + (uint32_t)(row * (LDA * 4) + fj * 16),
                           Brow + (size_t)(bnl + row) * LDB_G + k0 + fj * 4);
            }
        } else {
            const int kk = t >> 3, n4 = t & 7;   // [k][n] LDN=72 floats (288B)
            const float* src = Bg + bbase + (size_t)(k0 + kk) * 1024 + bn;
            CP_ASYNC16(sa + ABYTES + (uint32_t)(kk * 288 + n4 * 16),       src + n4 * 4);
            CP_ASYNC16(sa + ABYTES + (uint32_t)(kk * 288 + (n4 + 8) * 16), src + (n4 + 8) * 4);
        }
    };

    // ---- fragment loaders ----
    auto frag_a = [&](const float* As, int ks, uint32_t a[2][4]) {
        const int k = ks * 8;
#pragma unroll
        for (int mt = 0; mt < 2; mt++) {
            int r0 = (wm * 32 + mt * 16 + g) * LDA + k + tg;
            float a0 = As[r0], a1 = As[r0 + 8 * LDA];
            float a2 = As[r0 + 4], a3 = As[r0 + 8 * LDA + 4];
            if constexpr (CVT_A) {
                a0 = to_tf32(a0); a1 = to_tf32(a1);
                a2 = to_tf32(a2); a3 = to_tf32(a3);
            }
            a[mt][0] = __float_as_uint(a0); a[mt][1] = __float_as_uint(a1);
            a[mt][2] = __float_as_uint(a2); a[mt][3] = __float_as_uint(a3);
        }
    };
    auto frag_b = [&](const float* Bs, int ks, uint32_t b[4][2]) {
        const int k = ks * 8;
#pragma unroll
        for (int nt = 0; nt < 4; nt++) {
            const int n = wn * 32 + nt * 8 + g;
            float v0, v1;
            if constexpr (MODE <= 1) {
                int n0 = n * LDA + k + tg;
                v0 = Bs[n0]; v1 = Bs[n0 + 4];
            } else {
                int n0 = (k + tg) * LDN + n;
                v0 = Bs[n0]; v1 = Bs[n0 + 4 * LDN];
            }
            b[nt][0] = __float_as_uint(to_tf32(v0));
            b[nt][1] = __float_as_uint(to_tf32(v1));
        }
    };

    float acc[2][4][4];
#pragma unroll
    for (int mt = 0; mt < 2; mt++)
#pragma unroll
        for (int nt = 0; nt < 4; nt++)
#pragma unroll
            for (int q = 0; q < 4; q++) acc[mt][nt][q] = 0.f;

    // prologue
    fill(0); CP_COMMIT();

    for (int kc = 0; kc < NK; kc++) {
        CP_WAIT(0);            // drain fill(kc) (only outstanding group)
        __syncthreads();       // stage (kc+1)&1 free: compute(kc-1) done by all
        if (kc + 1 < NK) { fill(kc + 1); CP_COMMIT(); }

        const char* st = smem_buf + (kc & 1) * STAGE;
        const float* As = (const float*)st;
        const float* Bs = (const float*)(st + ABYTES);

#pragma unroll
        for (int ks = 0; ks < 4; ks++) {
            uint32_t a[2][4], b[4][2];
            frag_a(As, ks, a);
            frag_b(Bs, ks, b);
#pragma unroll
            for (int mt = 0; mt < 2; mt++)
#pragma unroll
                for (int nt = 0; nt < 4; nt++)
                    mma8(acc[mt][nt], a[mt], b[nt]);
        }
        __syncthreads();       // all warps done with stage kc before refill
    }

    // ---- epilogue ----
#pragma unroll
    for (int mt = 0; mt < 2; mt++) {
#pragma unroll
        for (int ro = 0; ro < 2; ro++) {
            int m = bm + wm * 32 + mt * 16 + g + ro * 8;
            bool wr = true; float scale = 1.f; float* rp = nullptr;
            if constexpr (MODE == 0) {
                rp = g_GU + (size_t)m * (2 * SHARED_FF) + bn;   // col base = bn
            } else if constexpr (MODE == 1) {
                rp = Cg + (size_t)m * HIDDEN + bn;
                scale = g_sig[m];
            } else {
                wr = (m < Me);
                int ent = lst[wr ? m : 0];
                if constexpr (MODE == 2) rp = g_GUe + (size_t)ent * HIDDEN + bn;
                else { rp = g_partial + (size_t)ent * HIDDEN + bn; scale = g_wts[ent]; }
            }
            if (wr) {
#pragma unroll
                for (int nt = 0; nt < 4; nt++) {
                    int col = wn * 32 + nt * 8 + 2 * tg;
                    float2 o;
                    o.x = acc[mt][nt][ro * 2 + 0] * scale;
                    o.y = acc[mt][nt][ro * 2 + 1] * scale;
                    *(float2*)(rp + col) = o;
                }
            }
        }
    }
}

// ---------------- SwiGLU fuse kernels (same arithmetic as old epilogues) ----
// g_H1[m][j] = tf32(silu(g_GU[m][j]) * g_GU[m][j+2816])
__global__ void k_fuse1() {
    int idx = blockIdx.x * blockDim.x + threadIdx.x;       // float4 index
    const int W = SHARED_FF / 4;                           // 704
    int m = idx / W, j4 = idx - m * W;
    const float4* gp = (const float4*)(g_GU + (size_t)m * (2 * SHARED_FF));
    float4 gv = gp[j4];
    float4 uv = gp[j4 + W];
    float4 o;
    o.x = to_tf32(silu_f(gv.x) * uv.x);
    o.y = to_tf32(silu_f(gv.y) * uv.y);
    o.z = to_tf32(silu_f(gv.z) * uv.z);
    o.w = to_tf32(silu_f(gv.w) * uv.w);
    ((float4*)(g_H1 + (size_t)m * SHARED_FF))[j4] = o;
}

// g_Hx[ent][j] = tf32(silu(g_GUe[ent][j]) * g_GUe[ent][j+512])
__global__ void k_fuse2() {
    int idx = blockIdx.x * blockDim.x + threadIdx.x;       // float4 index
    const int W = MOE_FF / 4;                              // 128
    int m = idx / W, j4 = idx - m * W;
    const float4* gp = (const float4*)(g_GUe + (size_t)m * HIDDEN);
    float4 gv = gp[j4];
    float4 uv = gp[j4 + W];
    float4 o;
    o.x = to_tf32(silu_f(gv.x) * uv.x);
    o.y = to_tf32(silu_f(gv.y) * uv.y);
    o.z = to_tf32(silu_f(gv.z) * uv.z);
    o.w = to_tf32(silu_f(gv.w) * uv.w);
    ((float4*)(g_Hx + (size_t)m * MOE_FF))[j4] = o;
}

// out += partial[2n] + partial[2n+1]
__global__ void k_combine(float* __restrict__ out) {
    int idx = blockIdx.x * blockDim.x + threadIdx.x;
    const int W = HIDDEN / 4;
    int n = idx / W;
    int c = idx - n * W;
    float4* o = (float4*)out;
    const float4* p = (const float4*)g_partial;
    float4 v  = o[idx];
    float4 p0 = p[(size_t)(2 * n) * W + c];
    float4 p1 = p[(size_t)(2 * n + 1) * W + c];
    v.x += p0.x + p1.x; v.y += p0.y + p1.y;
    v.z += p0.z + p1.z; v.w += p0.w + p1.w;
    o[idx] = v;
}

// ---------------- launch ----------------------------------------------------
extern "C" void kernel_launch(void* const* d_in, const int* in_sizes, int n_in,
                              void* d_out, int out_size) {
    const float* x    = (const float*)d_in[0];
    const float* gw   = (const float*)d_in[1];
    const float* wgu  = (const float*)d_in[2];
    const float* wdn  = (const float*)d_in[3];
    const float* swg  = (const float*)d_in[4];
    const float* swu  = (const float*)d_in[5];
    const float* swd  = (const float*)d_in[6];
    const float* sgw  = (const float*)d_in[7];
    float* out = (float*)d_out;

    const int SM_ALL = 2 * 27648;   // 55296 bytes, 3 CTAs/SM fit
    static bool init_done = false;
    static cudaStream_t s_exp;
    static cudaEvent_t ev_fork, ev_rt, ev_join;
    if (!init_done) {
        cudaFuncSetAttribute(k_mma<HIDDEN,    0>, cudaFuncAttributeMaxDynamicSharedMemorySize, SM_ALL);
        cudaFuncSetAttribute(k_mma<SHARED_FF, 1>, cudaFuncAttributeMaxDynamicSharedMemorySize, SM_ALL);
        cudaFuncSetAttribute(k_mma<HIDDEN,    2>, cudaFuncAttributeMaxDynamicSharedMemorySize, SM_ALL);
        cudaFuncSetAttribute(k_mma<MOE_FF,    3>, cudaFuncAttributeMaxDynamicSharedMemorySize, SM_ALL);
        cudaStreamCreateWithFlags(&s_exp, cudaStreamNonBlocking);
        cudaEventCreateWithFlags(&ev_fork, cudaEventDisableTiming);
        cudaEventCreateWithFlags(&ev_rt,   cudaEventDisableTiming);
        cudaEventCreateWithFlags(&ev_join, cudaEventDisableTiming);
        init_done = true;
    }

    // fork expert stream
    cudaEventRecord(ev_fork, 0);
    cudaStreamWaitEvent(s_exp, ev_fork, 0);

    // expert stream: router + expert chain
    k_zero_cnt<<<1, 32, 0, s_exp>>>();
    k_router<<<NTOK, 128, 0, s_exp>>>(x, gw, sgw);
    cudaEventRecord(ev_rt, s_exp);   // g_sig ready (needed by MODE1 epilogue)

    // expert gemm1: per-expert [Me x 1024] (gate|up in one matrix), K=1024
    k_mma<HIDDEN, 2><<<dim3(HIDDEN / 64, NTOK / 128, NE), 256, SM_ALL, s_exp>>>(
        x, wgu, nullptr, nullptr);
    k_fuse2<<<(NENT * MOE_FF / 4) / 256, 256, 0, s_exp>>>();
    // expert gemm2: per-expert [Me x 1024], K=512
    k_mma<MOE_FF, 3><<<dim3(HIDDEN / 64, NTOK / 128, NE), 256, SM_ALL, s_exp>>>(
        nullptr, wdn, nullptr, nullptr);
    cudaEventRecord(ev_join, s_exp);

    // main stream: shared gemm1 — gate blocks (bn<2816) use swg, up use swu
    k_mma<HIDDEN, 0><<<dim3(2 * SHARED_FF / 64, NTOK / 128), 256, SM_ALL>>>(
        x, swg, swu, nullptr);
    k_fuse1<<<(NTOK * SHARED_FF / 4) / 256, 256>>>();
    // shared gemm2 needs g_sig (router) — long done by now
    cudaStreamWaitEvent(0, ev_rt, 0);
    k_mma<SHARED_FF, 1><<<dim3(HIDDEN / 64, NTOK / 128), 256, SM_ALL>>>(
        nullptr, swd, nullptr, out);

    // join: combine needs both chains
    cudaStreamWaitEvent(0, ev_join, 0);
    k_combine<<<(NTOK * HIDDEN / 4) / 256, 256>>>(out);
}

// round 14
// speedup vs baseline: 1.0787x; 1.0787x over previous
#include <cuda_runtime.h>
#include <cstdint>

#define HIDDEN    1024
#define MOE_FF    512
#define SHARED_FF 2816
#define NE        16
#define NTOK      2048
#define NENT      (2*NTOK)

// ---------------- scratch (device globals; no allocation allowed) ----------
__device__ float g_H1[NTOK * SHARED_FF];     // shared-expert hidden (tf32-rounded)
__device__ float g_Hx[NENT * MOE_FF];        // expert hidden per entry (tf32-rounded)
__device__ float g_partial[NENT * HIDDEN];   // weighted expert out per entry
__device__ int   g_list[NE][NTOK];           // entry id (2n+k) per expert bucket
__device__ int   g_cnt[NE];
__device__ float g_wts[NENT];                // renormalized router weight per entry
__device__ float g_sig[NTOK];                // shared-expert sigmoid gate

__device__ __forceinline__ float silu_f(float v) { return v / (1.f + __expf(-v)); }
__device__ __forceinline__ float to_tf32(float x) {
    float y; asm("cvt.rna.tf32.f32 %0, %1;" : "=f"(y) : "f"(x)); return y;
}

// m16n8k8 TF32 HMMA (generic PTX — valid on target sm_103)
__device__ __forceinline__ void mma8(float* c, const uint32_t* a, const uint32_t* b) {
    asm volatile(
        "mma.sync.aligned.m16n8k8.row.col.f32.tf32.tf32.f32 "
        "{%0,%1,%2,%3}, {%4,%5,%6,%7}, {%8,%9}, {%0,%1,%2,%3};"
        : "+f"(c[0]), "+f"(c[1]), "+f"(c[2]), "+f"(c[3])
        : "r"(a[0]), "r"(a[1]), "r"(a[2]), "r"(a[3]), "r"(b[0]), "r"(b[1]));
}

__device__ __forceinline__ uint32_t smem_u32(const void* p) {
    uint32_t a;
    asm("{ .reg .u64 t; cvta.to.shared.u64 t, %1; cvt.u32.u64 %0, t; }" : "=r"(a) : "l"(p));
    return a;
}
#define CP_ASYNC16(dst, src) \
    asm volatile("cp.async.cg.shared.global [%0], [%1], 16;" :: "r"(dst), "l"(src))
#define CP_COMMIT() asm volatile("cp.async.commit_group;" ::: "memory")
#define CP_WAIT(n)  asm volatile("cp.async.wait_group %0;" :: "n"(n) : "memory")

// ---------------- misc ------------------------------------------------------
__global__ void k_zero_cnt() {
    if (threadIdx.x < NE) g_cnt[threadIdx.x] = 0;
}

// ---------------- router: logits -> top2 -> renorm weights + buckets --------
__global__ void k_router(const float* __restrict__ x,
                         const float* __restrict__ gw,
                         const float* __restrict__ sgw) {
    int n = blockIdx.x;
    int t = threadIdx.x;
    float xv[8];
#pragma unroll
    for (int i = 0; i < 8; i++) xv[i] = x[n * HIDDEN + t + i * 128];

    __shared__ float red[17 * 4];
    for (int e = 0; e < 17; e++) {
        const float* wr = (e < 16) ? (gw + e * HIDDEN) : sgw;
        float s = 0.f;
#pragma unroll
        for (int i = 0; i < 8; i++) s += xv[i] * wr[t + i * 128];
#pragma unroll
        for (int o = 16; o; o >>= 1) s += __shfl_xor_sync(0xffffffffu, s, o);
        if ((t & 31) == 0) red[e * 4 + (t >> 5)] = s;
    }
    __syncthreads();
    if (t == 0) {
        float lg[17];
        for (int e = 0; e < 17; e++)
            lg[e] = red[e * 4] + red[e * 4 + 1] + red[e * 4 + 2] + red[e * 4 + 3];
        int i0 = 0;
        for (int e = 1; e < 16; e++) if (lg[e] > lg[i0]) i0 = e;
        int i1 = -1;
        for (int e = 0; e < 16; e++) {
            if (e == i0) continue;
            if (i1 < 0 || lg[e] > lg[i1]) i1 = e;
        }
        float m  = lg[i0];
        float e0 = expf(lg[i0] - m);
        float e1 = expf(lg[i1] - m);
        float inv = 1.f / (e0 + e1);
        g_wts[2 * n]     = e0 * inv;
        g_wts[2 * n + 1] = e1 * inv;
        int p0 = atomicAdd(&g_cnt[i0], 1); g_list[i0][p0] = 2 * n;
        int p1 = atomicAdd(&g_cnt[i1], 1); g_list[i1][p1] = 2 * n + 1;
        g_sig[n] = 1.f / (1.f + expf(-lg[16]));
    }
}

// ---------------- TF32 HMMA GEMM, cp.async ring, 1 barrier/chunk ------------
// CTA 128xBN, 8 warps 4Mx2N. DUAL modes (0,2) and MODE1: BN=64; MODE3: BN=128.
// A smem [m][k] LDA=36; B smem modes 0/1 [n][k] LDA=36, modes 2/3 [k][n]
// LDN=BN+8. All fragment LDS conflict-free.
// Stages: MODE1 = 4 (deeper prefetch, K=2816); others = 3.
// MODE1 keeps full register frag double-buffering (FDB) and fuses the final
// combine: out = acc*sig + (partial[2m] + partial[2m+1])  (rounding order kept
// identical to the old k_combine via __fmul_rn/__fadd_rn).
template<int KTOT, bool DUAL, int MODE, int BN>
__global__ void __launch_bounds__(256, 2)
k_mma(const float* __restrict__ Ag, const float* __restrict__ Bg,
      const float* __restrict__ B2g, float* __restrict__ Cg)
{
    constexpr int NK      = KTOT / 32;
    constexpr int NSTAGE  = (MODE == 1) ? 4 : 3;
    constexpr int LDA     = 36;                         // floats
    constexpr int ABYTES  = 128 * LDA * 4;              // 18432
    constexpr int NT      = BN / 16;                    // n8-tiles per warp
    constexpr int WNW     = BN / 2;                     // warp N width
    constexpr int LDN     = BN + 8;                     // [k][n] stride, modes>=2
    constexpr int BBYTES  = (MODE <= 1) ? BN * LDA * 4 : 32 * LDN * 4;
    constexpr int STAGE   = ABYTES + BBYTES * (DUAL ? 2 : 1);
    constexpr bool CVT_A  = (MODE == 0 || MODE == 2);   // raw-fp32 A needs cvt
    constexpr int LDB_G   = (MODE == 0) ? HIDDEN : SHARED_FF; // modes 0/1 only
    constexpr bool FDB    = (!DUAL && BN == 64);        // full frag double-buffer

    extern __shared__ char smem_buf[];
    const uint32_t sb0 = smem_u32(smem_buf);

    const int t   = threadIdx.x;
    const int wid = t >> 5, lid = t & 31;
    const int wm  = wid & 3, wn = wid >> 2;
    const int g   = lid >> 2, tg = lid & 3;
    const int bn  = blockIdx.x * BN, bm = blockIdx.y * 128;

    int Me = 0; const int* lst = nullptr; size_t bbase = 0;
    if constexpr (MODE >= 2) {
        int e = blockIdx.z;
        Me = g_cnt[e];
        if (bm >= Me) return;
        lst = g_list[e];
        bbase = (size_t)e * KTOT * 1024;
    }

    // A fill assignment: thread covers rows fr+32i (i=0..3), 16B slot fj
    const int fj = t & 7, fr = t >> 3;
    const float* arow[4];
#pragma unroll
    for (int i = 0; i < 4; i++) {
        int row = fr + 32 * i;
        if constexpr (MODE == 0)      arow[i] = Ag   + (size_t)(bm + row) * HIDDEN;
        else if constexpr (MODE == 1) arow[i] = g_H1 + (size_t)(bm + row) * SHARED_FF;
        else {
            int m = bm + row; if (m > Me - 1) m = Me - 1;
            int ent = lst[m];
            if constexpr (MODE == 2) arow[i] = Ag   + (size_t)(ent >> 1) * HIDDEN;
            else                     arow[i] = g_Hx + (size_t)ent * MOE_FF;
        }
    }

    // ---- pipelined fill of one stage ----
    auto fill = [&](int kc) {
        const int k0 = kc * 32;
        const uint32_t sa = sb0 + (uint32_t)((kc % NSTAGE) * STAGE);
#pragma unroll
        for (int i = 0; i < 4; i++)
            CP_ASYNC16(sa + (uint32_t)((fr + 32 * i) * (LDA * 4) + fj * 16),
                       arow[i] + k0 + fj * 4);
        if constexpr (MODE <= 1) {
            // [n][k] rows: BN/32 rows per thread
#pragma unroll
            for (int i = 0; i < BN / 32; i++) {
                int row = fr + 32 * i;
                CP_ASYNC16(sa + ABYTES + (uint32_t)(row * (LDA * 4) + fj * 16),
                           Bg + (size_t)(bn + row) * LDB_G + k0 + fj * 4);
                if constexpr (DUAL)
                    CP_ASYNC16(sa + ABYTES + BBYTES + (uint32_t)(row * (LDA * 4) + fj * 16),
                               B2g + (size_t)(bn + row) * LDB_G + k0 + fj * 4);
            }
        } else {
            // [k][n]: 32 k-rows x BN floats; coalesced 16B chunks
            const int kk = t >> 3, n4 = t & 7;
            const float* src = Bg + bbase + (size_t)(k0 + kk) * 1024 + bn;
#pragma unroll
            for (int j = 0; j < BN / 32; j++) {
                int slot = n4 + 8 * j;
                CP_ASYNC16(sa + ABYTES + (uint32_t)(kk * (LDN * 4) + slot * 16),
                           src + slot * 4);
            }
            if constexpr (DUAL) {
                const float* src2 = src + 512;   // up-projection columns
#pragma unroll
                for (int j = 0; j < BN / 32; j++) {
                    int slot = n4 + 8 * j;
                    CP_ASYNC16(sa + ABYTES + BBYTES + (uint32_t)(kk * (LDN * 4) + slot * 16),
                               src2 + slot * 4);
                }
            }
        }
    };

    // ---- fragment loaders ----
    auto frag_a = [&](const float* As, int ks, uint32_t a[2][4]) {
        const int k = ks * 8;
#pragma unroll
        for (int mt = 0; mt < 2; mt++) {
            int r0 = (wm * 32 + mt * 16 + g) * LDA + k + tg;
            float a0 = As[r0], a1 = As[r0 + 8 * LDA];
            float a2 = As[r0 + 4], a3 = As[r0 + 8 * LDA + 4];
            if constexpr (CVT_A) {
                a0 = to_tf32(a0); a1 = to_tf32(a1);
                a2 = to_tf32(a2); a3 = to_tf32(a3);
            }
            a[mt][0] = __float_as_uint(a0); a[mt][1] = __float_as_uint(a1);
            a[mt][2] = __float_as_uint(a2); a[mt][3] = __float_as_uint(a3);
        }
    };
    auto frag_b = [&](const float* Bs, int ks, uint32_t b[NT][2]) {
        const int k = ks * 8;
#pragma unroll
        for (int nt = 0; nt < NT; nt++) {
            const int n = wn * WNW + nt * 8 + g;
            float v0, v1;
            if constexpr (MODE <= 1) {
                int n0 = n * LDA + k + tg;
                v0 = Bs[n0]; v1 = Bs[n0 + 4];
            } else {
                int n0 = (k + tg) * LDN + n;
                v0 = Bs[n0]; v1 = Bs[n0 + 4 * LDN];
            }
            b[nt][0] = __float_as_uint(to_tf32(v0));
            b[nt][1] = __float_as_uint(to_tf32(v1));
        }
    };

    float acc [2][NT][4];
    float acc2[DUAL ? 2 : 1][DUAL ? NT : 1][DUAL ? 4 : 1];
#pragma unroll
    for (int mt = 0; mt < 2; mt++)
#pragma unroll
        for (int nt = 0; nt < NT; nt++)
#pragma unroll
            for (int q = 0; q < 4; q++) {
                acc[mt][nt][q] = 0.f;
                if constexpr (DUAL) acc2[mt][nt][q] = 0.f;
            }

    // prologue: fill stages 0..NSTAGE-2
#pragma unroll
    for (int s = 0; s < NSTAGE - 1; s++) { fill(s); CP_COMMIT(); }

    for (int kc = 0; kc < NK; kc++) {
        // issued so far: fills through min(kc+NSTAGE-2, NK-1).
        // pend = groups newer than fill(kc) that may stay outstanding.
        {
            int last_issued = kc + NSTAGE - 2;
            if (last_issued > NK - 1) last_issued = NK - 1;
            const int pend = last_issued - kc;
            if (pend >= 2)      CP_WAIT(2);
            else if (pend == 1) CP_WAIT(1);
            else                CP_WAIT(0);
        }
        __syncthreads();
        // fill(kc+NSTAGE-1) targets stage (kc-1)%NSTAGE — free now
        if (kc + NSTAGE - 1 < NK) { fill(kc + NSTAGE - 1); CP_COMMIT(); }

        const char* st = smem_buf + (kc % NSTAGE) * STAGE;
        const float* As  = (const float*)st;
        const float* Bs  = (const float*)(st + ABYTES);
        const float* B2s = (const float*)(st + ABYTES + BBYTES);

        if constexpr (FDB) {
            // full register double-buffering (MODE1)
            uint32_t aP[2][2][4], bP[2][NT][2];
            frag_a(As, 0, aP[0]); frag_b(Bs, 0, bP[0]);
#pragma unroll
            for (int ks = 0; ks < 4; ks++) {
                const int cur = ks & 1, nxt = cur ^ 1;
                if (ks < 3) { frag_a(As, ks + 1, aP[nxt]); frag_b(Bs, ks + 1, bP[nxt]); }
#pragma unroll
                for (int mt = 0; mt < 2; mt++)
#pragma unroll
                    for (int nt = 0; nt < NT; nt++)
                        mma8(acc[mt][nt], aP[cur][mt], bP[cur][nt]);
            }
        } else {
#pragma unroll
            for (int ks = 0; ks < 4; ks++) {
                uint32_t a[2][4], b[NT][2];
                frag_a(As, ks, a);
                frag_b(Bs, ks, b);
#pragma unroll
                for (int mt = 0; mt < 2; mt++)
#pragma unroll
                    for (int nt = 0; nt < NT; nt++)
                        mma8(acc[mt][nt], a[mt], b[nt]);
                if constexpr (DUAL) {
                    uint32_t b2[NT][2];
                    frag_b(B2s, ks, b2);
#pragma unroll
                    for (int mt = 0; mt < 2; mt++)
#pragma unroll
                        for (int nt = 0; nt < NT; nt++)
                            mma8(acc2[mt][nt], a[mt], b2[nt]);
                }
            }
        }
    }

    // ---- epilogue ----
#pragma unroll
    for (int mt = 0; mt < 2; mt++) {
#pragma unroll
        for (int ro = 0; ro < 2; ro++) {
            int m = bm + wm * 32 + mt * 16 + g + ro * 8;
            bool wr = true; float scale = 1.f; float* rp = nullptr;
            const float* pp0 = nullptr; const float* pp1 = nullptr;
            if constexpr (MODE == 0) {
                rp = g_H1 + (size_t)m * SHARED_FF;
            } else if constexpr (MODE == 1) {
                rp = Cg + (size_t)m * HIDDEN;
                scale = g_sig[m];
                pp0 = g_partial + (size_t)(2 * m) * HIDDEN;
                pp1 = g_partial + (size_t)(2 * m + 1) * HIDDEN;
            } else {
                wr = (m < Me);
                int ent = lst[wr ? m : 0];
                if constexpr (MODE == 2) rp = g_Hx + (size_t)ent * MOE_FF;
                else { rp = g_partial + (size_t)ent * HIDDEN; scale = g_wts[ent]; }
            }
            if (wr) {
#pragma unroll
                for (int nt = 0; nt < NT; nt++) {
                    int col = bn + wn * WNW + nt * 8 + 2 * tg;
                    float x0 = acc[mt][nt][ro * 2 + 0];
                    float x1 = acc[mt][nt][ro * 2 + 1];
                    float2 o;
                    if constexpr (DUAL) {
                        // pre-round intermediates to tf32 so consumer skips cvt
                        o.x = to_tf32(silu_f(x0) * acc2[mt][nt][ro * 2 + 0]);
                        o.y = to_tf32(silu_f(x1) * acc2[mt][nt][ro * 2 + 1]);
                    } else if constexpr (MODE == 1) {
                        // fused combine: out = acc*sig + (p0 + p1)
                        // (rounding order identical to the old k_combine)
                        float2 p0 = *(const float2*)(pp0 + col);
                        float2 p1 = *(const float2*)(pp1 + col);
                        o.x = __fadd_rn(__fmul_rn(x0, scale), __fadd_rn(p0.x, p1.x));
                        o.y = __fadd_rn(__fmul_rn(x1, scale), __fadd_rn(p0.y, p1.y));
                    } else {
                        o.x = x0 * scale;
                        o.y = x1 * scale;
                    }
                    *(float2*)(rp + col) = o;
                }
            }
        }
    }
}

// ---------------- launch ----------------------------------------------------
extern "C" void kernel_launch(void* const* d_in, const int* in_sizes, int n_in,
                              void* d_out, int out_size) {
    const float* x    = (const float*)d_in[0];
    const float* gw   = (const float*)d_in[1];
    const float* wgu  = (const float*)d_in[2];
    const float* wdn  = (const float*)d_in[3];
    const float* swg  = (const float*)d_in[4];
    const float* swu  = (const float*)d_in[5];
    const float* swd  = (const float*)d_in[6];
    const float* sgw  = (const float*)d_in[7];
    float* out = (float*)d_out;

    // smem: dual = 3*(18432+2*9216)=110592 ; mode1 = 4*(18432+9216)=110592
    //       mode3 (BN=128, LDN=136) = 3*(18432+17408)=107520
    const int SM_DUAL = 3 * (18432 + 2 * 9216);
    const int SM_M1   = 4 * (18432 + 9216);
    const int SM_M3   = 3 * (18432 + 32 * 136 * 4);
    static bool init_done = false;
    static cudaStream_t s_exp;
    static cudaEvent_t ev_fork, ev_join;
    if (!init_done) {
        cudaFuncSetAttribute(k_mma<HIDDEN,    true,  0, 64 >, cudaFuncAttributeMaxDynamicSharedMemorySize, SM_DUAL);
        cudaFuncSetAttribute(k_mma<SHARED_FF, false, 1, 64 >, cudaFuncAttributeMaxDynamicSharedMemorySize, SM_M1);
        cudaFuncSetAttribute(k_mma<HIDDEN,    true,  2, 64 >, cudaFuncAttributeMaxDynamicSharedMemorySize, SM_DUAL);
        cudaFuncSetAttribute(k_mma<MOE_FF,    false, 3, 128>, cudaFuncAttributeMaxDynamicSharedMemorySize, SM_M3);
        cudaStreamCreateWithFlags(&s_exp, cudaStreamNonBlocking);
        cudaEventCreateWithFlags(&ev_fork, cudaEventDisableTiming);
        cudaEventCreateWithFlags(&ev_join, cudaEventDisableTiming);
        init_done = true;
    }

    // fork expert stream from the launch stream (required for graph capture)
    cudaEventRecord(ev_fork, 0);
    cudaStreamWaitEvent(s_exp, ev_fork, 0);

    // expert stream: router + expert chain
    k_zero_cnt<<<1, 32, 0, s_exp>>>();
    k_router<<<NTOK, 128, 0, s_exp>>>(x, gw, sgw);

    // expert gemm1: per-expert [Me x 512] dual, K=1024  (CTA 128x64)
    k_mma<HIDDEN, true, 2, 64><<<dim3(MOE_FF / 64, NTOK / 128, NE), 256, SM_DUAL, s_exp>>>(
        x, wgu, nullptr, nullptr);
    // expert gemm2: per-expert [Me x 1024], K=512       (CTA 128x128)
    k_mma<MOE_FF, false, 3, 128><<<dim3(HIDDEN / 128, NTOK / 128, NE), 256, SM_M3, s_exp>>>(
        nullptr, wdn, nullptr, nullptr);
    cudaEventRecord(ev_join, s_exp);

    // main stream: shared gemm1 starts immediately (no router dependency)
    k_mma<HIDDEN, true, 0, 64><<<dim3(SHARED_FF / 64, NTOK / 128), 256, SM_DUAL>>>(
        x, swg, swu, nullptr);

    // shared gemm2 fuses the combine: needs g_sig + g_partial (expert chain),
    // both long done by the time MODE0 finishes.
    cudaStreamWaitEvent(0, ev_join, 0);
    k_mma<SHARED_FF, false, 1, 64><<<dim3(HIDDEN / 64, NTOK / 128), 256, SM_M1>>>(
        nullptr, swd, nullptr, out);
}

// round 15
// speedup vs baseline: 1.2023x; 1.1146x over previous
#include <cuda_runtime.h>
#include <cstdint>

#define HIDDEN    1024
#define MOE_FF    512
#define SHARED_FF 2816
#define NE        16
#define NTOK      2048
#define NENT      (2*NTOK)

// ---------------- scratch (device globals; no allocation allowed) ----------
__device__ float g_H1[NTOK * SHARED_FF];     // shared-expert hidden (tf32-rounded)
__device__ float g_Hx[NENT * MOE_FF];        // expert hidden per entry (tf32-rounded)
__device__ float g_partial[NENT * HIDDEN];   // weighted expert out per entry
__device__ int   g_list[NE][NTOK];           // entry id (2n+k) per expert bucket
__device__ int   g_cnt[NE];
__device__ float g_wts[NENT];                // renormalized router weight per entry
__device__ float g_sig[NTOK];                // shared-expert sigmoid gate

__device__ __forceinline__ float silu_f(float v) { return v / (1.f + __expf(-v)); }
__device__ __forceinline__ float to_tf32(float x) {
    float y; asm("cvt.rna.tf32.f32 %0, %1;" : "=f"(y) : "f"(x)); return y;
}

// m16n8k8 TF32 HMMA (generic PTX — valid on target sm_103)
__device__ __forceinline__ void mma8(float* c, const uint32_t* a, const uint32_t* b) {
    asm volatile(
        "mma.sync.aligned.m16n8k8.row.col.f32.tf32.tf32.f32 "
        "{%0,%1,%2,%3}, {%4,%5,%6,%7}, {%8,%9}, {%0,%1,%2,%3};"
        : "+f"(c[0]), "+f"(c[1]), "+f"(c[2]), "+f"(c[3])
        : "r"(a[0]), "r"(a[1]), "r"(a[2]), "r"(a[3]), "r"(b[0]), "r"(b[1]));
}

__device__ __forceinline__ uint32_t smem_u32(const void* p) {
    uint32_t a;
    asm("{ .reg .u64 t; cvta.to.shared.u64 t, %1; cvt.u32.u64 %0, t; }" : "=r"(a) : "l"(p));
    return a;
}
#define CP_ASYNC16(dst, src) \
    asm volatile("cp.async.cg.shared.global [%0], [%1], 16;" :: "r"(dst), "l"(src))
#define CP_COMMIT() asm volatile("cp.async.commit_group;" ::: "memory")
#define CP_WAIT(n)  asm volatile("cp.async.wait_group %0;" :: "n"(n) : "memory")

// ---------------- misc ------------------------------------------------------
__global__ void k_zero_cnt() {
    if (threadIdx.x < NE) g_cnt[threadIdx.x] = 0;
}

// ---------------- router: logits -> top2 -> renorm weights + buckets --------
__global__ void k_router(const float* __restrict__ x,
                         const float* __restrict__ gw,
                         const float* __restrict__ sgw) {
    int n = blockIdx.x;
    int t = threadIdx.x;
    float xv[8];
#pragma unroll
    for (int i = 0; i < 8; i++) xv[i] = x[n * HIDDEN + t + i * 128];

    __shared__ float red[17 * 4];
    for (int e = 0; e < 17; e++) {
        const float* wr = (e < 16) ? (gw + e * HIDDEN) : sgw;
        float s = 0.f;
#pragma unroll
        for (int i = 0; i < 8; i++) s += xv[i] * wr[t + i * 128];
#pragma unroll
        for (int o = 16; o; o >>= 1) s += __shfl_xor_sync(0xffffffffu, s, o);
        if ((t & 31) == 0) red[e * 4 + (t >> 5)] = s;
    }
    __syncthreads();
    if (t == 0) {
        float lg[17];
        for (int e = 0; e < 17; e++)
            lg[e] = red[e * 4] + red[e * 4 + 1] + red[e * 4 + 2] + red[e * 4 + 3];
        int i0 = 0;
        for (int e = 1; e < 16; e++) if (lg[e] > lg[i0]) i0 = e;
        int i1 = -1;
        for (int e = 0; e < 16; e++) {
            if (e == i0) continue;
            if (i1 < 0 || lg[e] > lg[i1]) i1 = e;
        }
        float m  = lg[i0];
        float e0 = expf(lg[i0] - m);
        float e1 = expf(lg[i1] - m);
        float inv = 1.f / (e0 + e1);
        g_wts[2 * n]     = e0 * inv;
        g_wts[2 * n + 1] = e1 * inv;
        int p0 = atomicAdd(&g_cnt[i0], 1); g_list[i0][p0] = 2 * n;
        int p1 = atomicAdd(&g_cnt[i1], 1); g_list[i1][p1] = 2 * n + 1;
        g_sig[n] = 1.f / (1.f + expf(-lg[16]));
    }
}

// ---------------- TF32 HMMA GEMM, 3-stage cp.async ring, 1 barrier/chunk ----
// CTA 128xBN, 8 warps 4Mx2N. DUAL modes (0,2) and MODE1: BN=64; MODE3: BN=128.
// A smem [m][k] LDA=36; B smem modes 0/1 [n][k] LDA=36, modes 2/3 [k][n]
// LDN=BN+8. All fragment LDS conflict-free.
// MODE1 keeps full register frag double-buffering (FDB).
// Expert modes (2/3): warps whose whole 32-row m-range is >= Me skip fragment
// loads + MMAs (their acc is never written); they still run fills + barriers.
template<int KTOT, bool DUAL, int MODE, int BN>
__global__ void __launch_bounds__(256, 2)
k_mma(const float* __restrict__ Ag, const float* __restrict__ Bg,
      const float* __restrict__ B2g, float* __restrict__ Cg)
{
    constexpr int NK      = KTOT / 32;
    constexpr int NSTAGE  = 3;
    constexpr int LDA     = 36;                         // floats
    constexpr int ABYTES  = 128 * LDA * 4;              // 18432
    constexpr int NT      = BN / 16;                    // n8-tiles per warp
    constexpr int WNW     = BN / 2;                     // warp N width
    constexpr int LDN     = BN + 8;                     // [k][n] stride, modes>=2
    constexpr int BBYTES  = (MODE <= 1) ? BN * LDA * 4 : 32 * LDN * 4;
    constexpr int STAGE   = ABYTES + BBYTES * (DUAL ? 2 : 1);
    constexpr bool CVT_A  = (MODE == 0 || MODE == 2);   // raw-fp32 A needs cvt
    constexpr int LDB_G   = (MODE == 0) ? HIDDEN : SHARED_FF; // modes 0/1 only
    constexpr bool FDB    = (!DUAL && BN == 64);        // full frag double-buffer

    extern __shared__ char smem_buf[];
    const uint32_t sb0 = smem_u32(smem_buf);

    const int t   = threadIdx.x;
    const int wid = t >> 5, lid = t & 31;
    const int wm  = wid & 3, wn = wid >> 2;
    const int g   = lid >> 2, tg = lid & 3;
    const int bn  = blockIdx.x * BN, bm = blockIdx.y * 128;

    int Me = 0; const int* lst = nullptr; size_t bbase = 0;
    bool warp_active = true;
    if constexpr (MODE >= 2) {
        int e = blockIdx.z;
        Me = g_cnt[e];
        if (bm >= Me) return;
        lst = g_list[e];
        bbase = (size_t)e * KTOT * 1024;
        warp_active = (bm + wm * 32 < Me);   // whole warp m-range vs Me
    }

    // A fill assignment: thread covers rows fr+32i (i=0..3), 16B slot fj
    const int fj = t & 7, fr = t >> 3;
    const float* arow[4];
#pragma unroll
    for (int i = 0; i < 4; i++) {
        int row = fr + 32 * i;
        if constexpr (MODE == 0)      arow[i] = Ag   + (size_t)(bm + row) * HIDDEN;
        else if constexpr (MODE == 1) arow[i] = g_H1 + (size_t)(bm + row) * SHARED_FF;
        else {
            int m = bm + row; if (m > Me - 1) m = Me - 1;
            int ent = lst[m];
            if constexpr (MODE == 2) arow[i] = Ag   + (size_t)(ent >> 1) * HIDDEN;
            else                     arow[i] = g_Hx + (size_t)ent * MOE_FF;
        }
    }

    // ---- pipelined fill of one stage ----
    auto fill = [&](int kc) {
        const int k0 = kc * 32;
        const uint32_t sa = sb0 + (uint32_t)((kc % NSTAGE) * STAGE);
#pragma unroll
        for (int i = 0; i < 4; i++)
            CP_ASYNC16(sa + (uint32_t)((fr + 32 * i) * (LDA * 4) + fj * 16),
                       arow[i] + k0 + fj * 4);
        if constexpr (MODE <= 1) {
            // [n][k] rows: BN/32 rows per thread
#pragma unroll
            for (int i = 0; i < BN / 32; i++) {
                int row = fr + 32 * i;
                CP_ASYNC16(sa + ABYTES + (uint32_t)(row * (LDA * 4) + fj * 16),
                           Bg + (size_t)(bn + row) * LDB_G + k0 + fj * 4);
                if constexpr (DUAL)
                    CP_ASYNC16(sa + ABYTES + BBYTES + (uint32_t)(row * (LDA * 4) + fj * 16),
                               B2g + (size_t)(bn + row) * LDB_G + k0 + fj * 4);
            }
        } else {
            // [k][n]: 32 k-rows x BN floats; coalesced 16B chunks
            const int kk = t >> 3, n4 = t & 7;
            const float* src = Bg + bbase + (size_t)(k0 + kk) * 1024 + bn;
#pragma unroll
            for (int j = 0; j < BN / 32; j++) {
                int slot = n4 + 8 * j;
                CP_ASYNC16(sa + ABYTES + (uint32_t)(kk * (LDN * 4) + slot * 16),
                           src + slot * 4);
            }
            if constexpr (DUAL) {
                const float* src2 = src + 512;   // up-projection columns
#pragma unroll
                for (int j = 0; j < BN / 32; j++) {
                    int slot = n4 + 8 * j;
                    CP_ASYNC16(sa + ABYTES + BBYTES + (uint32_t)(kk * (LDN * 4) + slot * 16),
                               src2 + slot * 4);
                }
            }
        }
    };

    // ---- fragment loaders ----
    auto frag_a = [&](const float* As, int ks, uint32_t a[2][4]) {
        const int k = ks * 8;
#pragma unroll
        for (int mt = 0; mt < 2; mt++) {
            int r0 = (wm * 32 + mt * 16 + g) * LDA + k + tg;
            float a0 = As[r0], a1 = As[r0 + 8 * LDA];
            float a2 = As[r0 + 4], a3 = As[r0 + 8 * LDA + 4];
            if constexpr (CVT_A) {
                a0 = to_tf32(a0); a1 = to_tf32(a1);
                a2 = to_tf32(a2); a3 = to_tf32(a3);
            }
            a[mt][0] = __float_as_uint(a0); a[mt][1] = __float_as_uint(a1);
            a[mt][2] = __float_as_uint(a2); a[mt][3] = __float_as_uint(a3);
        }
    };
    auto frag_b = [&](const float* Bs, int ks, uint32_t b[NT][2]) {
        const int k = ks * 8;
#pragma unroll
        for (int nt = 0; nt < NT; nt++) {
            const int n = wn * WNW + nt * 8 + g;
            float v0, v1;
            if constexpr (MODE <= 1) {
                int n0 = n * LDA + k + tg;
                v0 = Bs[n0]; v1 = Bs[n0 + 4];
            } else {
                int n0 = (k + tg) * LDN + n;
                v0 = Bs[n0]; v1 = Bs[n0 + 4 * LDN];
            }
            b[nt][0] = __float_as_uint(to_tf32(v0));
            b[nt][1] = __float_as_uint(to_tf32(v1));
        }
    };

    float acc [2][NT][4];
    float acc2[DUAL ? 2 : 1][DUAL ? NT : 1][DUAL ? 4 : 1];
#pragma unroll
    for (int mt = 0; mt < 2; mt++)
#pragma unroll
        for (int nt = 0; nt < NT; nt++)
#pragma unroll
            for (int q = 0; q < 4; q++) {
                acc[mt][nt][q] = 0.f;
                if constexpr (DUAL) acc2[mt][nt][q] = 0.f;
            }

    // prologue: fill stages 0..NSTAGE-2
#pragma unroll
    for (int s = 0; s < NSTAGE - 1; s++) { fill(s); CP_COMMIT(); }

    for (int kc = 0; kc < NK; kc++) {
        // wait for own groups through fill(kc); barrier publishes all threads'
        if (kc < NK - 1) CP_WAIT(1);
        else             CP_WAIT(0);
        __syncthreads();
        // fill(kc+2) targets stage (kc-1)%3 — free now (barrier passed)
        if (kc + NSTAGE - 1 < NK) { fill(kc + NSTAGE - 1); CP_COMMIT(); }

        const char* st = smem_buf + (kc % NSTAGE) * STAGE;
        const float* As  = (const float*)st;
        const float* Bs  = (const float*)(st + ABYTES);
        const float* B2s = (const float*)(st + ABYTES + BBYTES);

        if constexpr (FDB) {
            // full register double-buffering (MODE1)
            uint32_t aP[2][2][4], bP[2][NT][2];
            frag_a(As, 0, aP[0]); frag_b(Bs, 0, bP[0]);
#pragma unroll
            for (int ks = 0; ks < 4; ks++) {
                const int cur = ks & 1, nxt = cur ^ 1;
                if (ks < 3) { frag_a(As, ks + 1, aP[nxt]); frag_b(Bs, ks + 1, bP[nxt]); }
#pragma unroll
                for (int mt = 0; mt < 2; mt++)
#pragma unroll
                    for (int nt = 0; nt < NT; nt++)
                        mma8(acc[mt][nt], aP[cur][mt], bP[cur][nt]);
            }
        } else if (warp_active) {
            // expert-mode warps with no live rows skip all compute (their acc
            // is never stored); fills + barriers above remain uniform.
#pragma unroll
            for (int ks = 0; ks < 4; ks++) {
                uint32_t a[2][4], b[NT][2];
                frag_a(As, ks, a);
                frag_b(Bs, ks, b);
#pragma unroll
                for (int mt = 0; mt < 2; mt++)
#pragma unroll
                    for (int nt = 0; nt < NT; nt++)
                        mma8(acc[mt][nt], a[mt], b[nt]);
                if constexpr (DUAL) {
                    uint32_t b2[NT][2];
                    frag_b(B2s, ks, b2);
#pragma unroll
                    for (int mt = 0; mt < 2; mt++)
#pragma unroll
                        for (int nt = 0; nt < NT; nt++)
                            mma8(acc2[mt][nt], a[mt], b2[nt]);
                }
            }
        }
    }

    // ---- epilogue ----
#pragma unroll
    for (int mt = 0; mt < 2; mt++) {
#pragma unroll
        for (int ro = 0; ro < 2; ro++) {
            int m = bm + wm * 32 + mt * 16 + g + ro * 8;
            bool wr = true; float scale = 1.f; float* rp = nullptr;
            if constexpr (MODE == 0) {
                rp = g_H1 + (size_t)m * SHARED_FF;
            } else if constexpr (MODE == 1) {
                rp = Cg + (size_t)m * HIDDEN;
                scale = g_sig[m];
            } else {
                wr = (m < Me);
                int ent = lst[wr ? m : 0];
                if constexpr (MODE == 2) rp = g_Hx + (size_t)ent * MOE_FF;
                else { rp = g_partial + (size_t)ent * HIDDEN; scale = g_wts[ent]; }
            }
            if (wr) {
#pragma unroll
                for (int nt = 0; nt < NT; nt++) {
                    int col = bn + wn * WNW + nt * 8 + 2 * tg;
                    float x0 = acc[mt][nt][ro * 2 + 0];
                    float x1 = acc[mt][nt][ro * 2 + 1];
                    float2 o;
                    if constexpr (DUAL) {
                        // pre-round intermediates to tf32 so consumer skips cvt
                        o.x = to_tf32(silu_f(x0) * acc2[mt][nt][ro * 2 + 0]);
                        o.y = to_tf32(silu_f(x1) * acc2[mt][nt][ro * 2 + 1]);
                    } else {
                        o.x = x0 * scale;
                        o.y = x1 * scale;
                    }
                    *(float2*)(rp + col) = o;
                }
            }
        }
    }
}

// out += partial[2n] + partial[2n+1]
__global__ void k_combine(float* __restrict__ out) {
    int idx = blockIdx.x * blockDim.x + threadIdx.x;
    const int W = HIDDEN / 4;
    int n = idx / W;
    int c = idx - n * W;
    float4* o = (float4*)out;
    const float4* p = (const float4*)g_partial;
    float4 v  = o[idx];
    float4 p0 = p[(size_t)(2 * n) * W + c];
    float4 p1 = p[(size_t)(2 * n + 1) * W + c];
    v.x += p0.x + p1.x; v.y += p0.y + p1.y;
    v.z += p0.z + p1.z; v.w += p0.w + p1.w;
    o[idx] = v;
}

// ---------------- launch ----------------------------------------------------
extern "C" void kernel_launch(void* const* d_in, const int* in_sizes, int n_in,
                              void* d_out, int out_size) {
    const float* x    = (const float*)d_in[0];
    const float* gw   = (const float*)d_in[1];
    const float* wgu  = (const float*)d_in[2];
    const float* wdn  = (const float*)d_in[3];
    const float* swg  = (const float*)d_in[4];
    const float* swu  = (const float*)d_in[5];
    const float* swd  = (const float*)d_in[6];
    const float* sgw  = (const float*)d_in[7];
    float* out = (float*)d_out;

    // smem: dual = 3*(18432+2*9216)=110592 ; mode1 = 3*(18432+9216)=82944
    //       mode3 (BN=128, LDN=136) = 3*(18432+17408)=107520
    const int SM_DUAL = 3 * (18432 + 2 * 9216);
    const int SM_M1   = 3 * (18432 + 9216);
    const int SM_M3   = 3 * (18432 + 32 * 136 * 4);
    static bool init_done = false;
    static cudaStream_t s_exp;
    static cudaEvent_t ev_fork, ev_rt, ev_join;
    if (!init_done) {
        cudaFuncSetAttribute(k_mma<HIDDEN,    true,  0, 64 >, cudaFuncAttributeMaxDynamicSharedMemorySize, SM_DUAL);
        cudaFuncSetAttribute(k_mma<SHARED_FF, false, 1, 64 >, cudaFuncAttributeMaxDynamicSharedMemorySize, SM_M1);
        cudaFuncSetAttribute(k_mma<HIDDEN,    true,  2, 64 >, cudaFuncAttributeMaxDynamicSharedMemorySize, SM_DUAL);
        cudaFuncSetAttribute(k_mma<MOE_FF,    false, 3, 128>, cudaFuncAttributeMaxDynamicSharedMemorySize, SM_M3);
        cudaStreamCreateWithFlags(&s_exp, cudaStreamNonBlocking);
        cudaEventCreateWithFlags(&ev_fork, cudaEventDisableTiming);
        cudaEventCreateWithFlags(&ev_rt,   cudaEventDisableTiming);
        cudaEventCreateWithFlags(&ev_join, cudaEventDisableTiming);
        init_done = true;
    }

    // fork expert stream from the launch stream (required for graph capture)
    cudaEventRecord(ev_fork, 0);
    cudaStreamWaitEvent(s_exp, ev_fork, 0);

    // expert stream: router + expert chain (MODE0 does not need the router)
    k_zero_cnt<<<1, 32, 0, s_exp>>>();
    k_router<<<NTOK, 128, 0, s_exp>>>(x, gw, sgw);
    cudaEventRecord(ev_rt, s_exp);   // g_sig ready (needed by MODE1 epilogue)

    // expert gemm1: per-expert [Me x 512] dual, K=1024  (CTA 128x64)
    k_mma<HIDDEN, true, 2, 64><<<dim3(MOE_FF / 64, NTOK / 128, NE), 256, SM_DUAL, s_exp>>>(
        x, wgu, nullptr, nullptr);
    // expert gemm2: per-expert [Me x 1024], K=512       (CTA 128x128)
    k_mma<MOE_FF, false, 3, 128><<<dim3(HIDDEN / 128, NTOK / 128, NE), 256, SM_M3, s_exp>>>(
        nullptr, wdn, nullptr, nullptr);
    cudaEventRecord(ev_join, s_exp);

    // main stream: shared gemm1 starts immediately (no router dependency)
    k_mma<HIDDEN, true, 0, 64><<<dim3(SHARED_FF / 64, NTOK / 128), 256, SM_DUAL>>>(
        x, swg, swu, nullptr);
    // shared gemm2 needs g_sig (router) — wait costs nothing, router is long done
    cudaStreamWaitEvent(0, ev_rt, 0);
    k_mma<SHARED_FF, false, 1, 64><<<dim3(HIDDEN / 64, NTOK / 128), 256, SM_M1>>>(
        nullptr, swd, nullptr, out);

    // join: combine needs both chains
    cudaStreamWaitEvent(0, ev_join, 0);
    k_combine<<<(NTOK * HIDDEN / 4) / 256, 256>>>(out);
}